// round 6
// baseline (speedup 1.0000x reference)
#include <cuda_runtime.h>

#define BB 16
#define LL 2048
#define DD 192
#define HH 4
#define KH 12
#define HK 48
#define LEPS 1e-3f
#define CR 16
#define RB 32

typedef unsigned long long u64;

// -------- scratch (no allocations allowed; __device__ globals) --------
__device__ float g_q[BB * HH * LL * KH];
__device__ float g_k[BB * HH * LL * KH];
__device__ float g_v[BB * HH * LL * KH];
__device__ float g_ctx[BB * HH * LL * KH];
__device__ float g_y1[BB * LL * DD];
__device__ float g_xn2[BB * LL * DD];
__device__ float g_hp[BB * LL * DD];

// -------- packed fp32x2 helpers --------
__device__ __forceinline__ u64 ffma2(u64 a, u64 b, u64 c) {
    u64 d; asm("fma.rn.f32x2 %0, %1, %2, %3;" : "=l"(d) : "l"(a), "l"(b), "l"(c));
    return d;
}
__device__ __forceinline__ u64 fmul2(u64 a, u64 b) {
    u64 d; asm("mul.rn.f32x2 %0, %1, %2;" : "=l"(d) : "l"(a), "l"(b));
    return d;
}
__device__ __forceinline__ u64 pack2(float lo, float hi) {
    u64 r; asm("mov.b64 %0, {%1, %2};" : "=l"(r) : "f"(lo), "f"(hi));
    return r;
}
__device__ __forceinline__ float2 unpack2(u64 v) {
    float2 f; asm("mov.b64 {%0, %1}, %2;" : "=f"(f.x), "=f"(f.y) : "l"(v));
    return f;
}
__device__ __forceinline__ float fast_ex2(float x) {
    float y; asm("ex2.approx.f32 %0, %1;" : "=f"(y) : "f"(x)); return y;
}

// ======================= K1: LN1 + QKV projection =======================
__global__ void __launch_bounds__(288) k_ln1_qkv(
    const float* __restrict__ x,
    const float* __restrict__ ln_g, const float* __restrict__ ln_b,
    const float* __restrict__ wq, const float* __restrict__ bq,
    const float* __restrict__ wk, const float* __restrict__ bk,
    const float* __restrict__ wv, const float* __restrict__ bv)
{
    __shared__ float xsT[DD][RB + 2];
    __shared__ float mean_s[RB], rstd_s[RB];
    const int row0 = blockIdx.x * RB;
    const int tid  = threadIdx.x;

    for (int idx = tid; idx < RB * DD; idx += 288) {
        const int r = idx / DD, c = idx - r * DD;
        xsT[c][r] = x[(row0 + r) * DD + c];
    }
    __syncthreads();

    if (tid < RB) {
        float s = 0.f, s2 = 0.f;
        #pragma unroll 8
        for (int c = 0; c < DD; c++) {
            const float v = xsT[c][tid];
            s += v; s2 = fmaf(v, v, s2);
        }
        const float m = s * (1.0f / DD);
        const float var = s2 * (1.0f / DD) - m * m;
        mean_s[tid] = m;
        rstd_s[tid] = rsqrtf(var + LEPS);
    }
    __syncthreads();

    for (int idx = tid; idx < RB * DD; idx += 288) {
        const int r = idx & (RB - 1), c = idx >> 5;
        xsT[c][r] = (xsT[c][r] - mean_s[r]) * rstd_s[r] * ln_g[c] + ln_b[c];
    }
    __syncthreads();

    const int jj = tid % 144;
    const int rg = tid / 144;
    const int m  = jj / HK;
    const int j  = jj - m * HK;
    const float* w  = (m == 0) ? wq : (m == 1) ? wk : wv;
    const float* bb = (m == 0) ? bq : (m == 1) ? bk : bv;
    const float bias = bb[j];
    const int rbase = rg * 16;

    u64 acc[8];
    const u64 binit = pack2(bias, bias);
    #pragma unroll
    for (int p = 0; p < 8; p++) acc[p] = binit;

    #pragma unroll 4
    for (int d = 0; d < DD; d++) {
        const float wv_ = w[d * HK + j];
        const u64 w2 = pack2(wv_, wv_);
        const u64* xp = (const u64*)&xsT[d][rbase];
        #pragma unroll
        for (int p = 0; p < 8; p++) acc[p] = ffma2(xp[p], w2, acc[p]);
    }

    float* dst = (m == 0) ? g_q : (m == 1) ? g_k : g_v;
    const int bi = row0 / LL;
    const int l0 = row0 - bi * LL;
    const int h = j / KH, kk = j - h * KH;
    float* o = dst + (((bi * HH + h) * LL) + l0 + rbase) * KH + kk;
    #pragma unroll
    for (int p = 0; p < 8; p++) {
        const float2 f = unpack2(acc[p]);
        o[(2 * p) * KH]     = f.x;
        o[(2 * p + 1) * KH] = f.y;
    }
}

// ======================= K2: causal attention, 2 queries/thread =======================
__device__ __forceinline__ void att_step(const u64* __restrict__ kp,
                                         const u64* __restrict__ vp,
                                         const u64* __restrict__ q2,
                                         u64* __restrict__ acc, float& ssum)
{
    u64 s2 = fmul2(q2[0], kp[0]);
    s2 = ffma2(q2[1], kp[1], s2);
    s2 = ffma2(q2[2], kp[2], s2);
    s2 = ffma2(q2[3], kp[3], s2);
    s2 = ffma2(q2[4], kp[4], s2);
    s2 = ffma2(q2[5], kp[5], s2);
    const float2 sf = unpack2(s2);
    const float p = fast_ex2(sf.x + sf.y);
    ssum += p;
    const u64 p2 = pack2(p, p);
    acc[0] = ffma2(p2, vp[0], acc[0]);
    acc[1] = ffma2(p2, vp[1], acc[1]);
    acc[2] = ffma2(p2, vp[2], acc[2]);
    acc[3] = ffma2(p2, vp[3], acc[3]);
    acc[4] = ffma2(p2, vp[4], acc[4]);
    acc[5] = ffma2(p2, vp[5], acc[5]);
}

__global__ void __launch_bounds__(128) k_attn()
{
    __shared__ float ks[128 * 12];
    __shared__ float vs[128 * 12];
    const int bh  = blockIdx.x;
    const int T0  = blockIdx.y * 2;
    const int T1  = T0 + 1;
    const int tid = threadIdx.x;
    const int l0  = T0 * 128 + tid;
    const int l1  = l0 + 128;

    const float qsc = 0.41647020f;    // log2(e) / sqrt(12)
    const u64 qsc2 = pack2(qsc, qsc);
    u64 q20[6], q21[6];
    {
        const u64* qp0 = (const u64*)(g_q + (bh * LL + l0) * KH);
        const u64* qp1 = (const u64*)(g_q + (bh * LL + l1) * KH);
        #pragma unroll
        for (int i = 0; i < 6; i++) { q20[i] = fmul2(qp0[i], qsc2); q21[i] = fmul2(qp1[i], qsc2); }
    }

    u64 acc0[6], acc1[6];
    #pragma unroll
    for (int i = 0; i < 6; i++) { acc0[i] = 0ull; acc1[i] = 0ull; }
    float ssum0 = 0.f, ssum1 = 0.f;

    for (int kt = 0; kt <= T1; kt++) {
        const float4* kp4 = (const float4*)(g_k + (bh * LL + kt * 128) * KH);
        const float4* vp4 = (const float4*)(g_v + (bh * LL + kt * 128) * KH);
        __syncthreads();
        ((float4*)ks)[tid * 3 + 0] = kp4[tid * 3 + 0];
        ((float4*)ks)[tid * 3 + 1] = kp4[tid * 3 + 1];
        ((float4*)ks)[tid * 3 + 2] = kp4[tid * 3 + 2];
        ((float4*)vs)[tid * 3 + 0] = vp4[tid * 3 + 0];
        ((float4*)vs)[tid * 3 + 1] = vp4[tid * 3 + 1];
        ((float4*)vs)[tid * 3 + 2] = vp4[tid * 3 + 2];
        __syncthreads();

        if (kt < T0) {
            #pragma unroll 2
            for (int m = 0; m < 128; m++) {
                const u64* kp = (const u64*)(ks + m * 12);
                const u64* vp = (const u64*)(vs + m * 12);
                att_step(kp, vp, q20, acc0, ssum0);
                att_step(kp, vp, q21, acc1, ssum1);
            }
        } else if (kt == T0) {
            for (int m = 0; m <= tid; m++) {
                const u64* kp = (const u64*)(ks + m * 12);
                const u64* vp = (const u64*)(vs + m * 12);
                att_step(kp, vp, q20, acc0, ssum0);
                att_step(kp, vp, q21, acc1, ssum1);
            }
            for (int m = tid + 1; m < 128; m++) {
                const u64* kp = (const u64*)(ks + m * 12);
                const u64* vp = (const u64*)(vs + m * 12);
                att_step(kp, vp, q21, acc1, ssum1);
            }
        } else {
            for (int m = 0; m <= tid; m++) {
                const u64* kp = (const u64*)(ks + m * 12);
                const u64* vp = (const u64*)(vs + m * 12);
                att_step(kp, vp, q21, acc1, ssum1);
            }
        }
    }

    const float inv0 = 1.0f / ssum0;
    const float inv1 = 1.0f / ssum1;
    const u64 i20 = pack2(inv0, inv0);
    const u64 i21 = pack2(inv1, inv1);
    u64* cp0 = (u64*)(g_ctx + (bh * LL + l0) * KH);
    u64* cp1 = (u64*)(g_ctx + (bh * LL + l1) * KH);
    #pragma unroll
    for (int i = 0; i < 6; i++) { cp0[i] = fmul2(acc0[i], i20); cp1[i] = fmul2(acc1[i], i21); }
}

// ======================= K3: out-proj + residual + LN2 =======================
__global__ void __launch_bounds__(DD) k_proj_ln2(
    const float* __restrict__ x,
    const float* __restrict__ wo, const float* __restrict__ bo,
    const float* __restrict__ g2, const float* __restrict__ b2)
{
    __shared__ float cs[HK];
    __shared__ float red[8];
    const int row = blockIdx.x;
    const int tid = threadIdx.x;
    const int bi = row / LL, l = row % LL;

    if (tid < HK) {
        const int h = tid / KH, kk = tid % KH;
        cs[tid] = g_ctx[((bi * HH + h) * LL + l) * KH + kk];
    }
    __syncthreads();

    float y = x[row * DD + tid] + bo[tid];
    #pragma unroll 8
    for (int j = 0; j < HK; j++) y = fmaf(cs[j], wo[j * DD + tid], y);
    g_y1[row * DD + tid] = y;

    float s = y;
    #pragma unroll
    for (int o = 16; o > 0; o >>= 1) s += __shfl_xor_sync(0xffffffffu, s, o);
    if ((tid & 31) == 0) red[tid >> 5] = s;
    __syncthreads();
    const float mean = (red[0] + red[1] + red[2] + red[3] + red[4] + red[5]) * (1.0f / DD);
    const float d0 = y - mean;
    __syncthreads();
    float s2 = d0 * d0;
    #pragma unroll
    for (int o = 16; o > 0; o >>= 1) s2 += __shfl_xor_sync(0xffffffffu, s2, o);
    if ((tid & 31) == 0) red[tid >> 5] = s2;
    __syncthreads();
    const float var = (red[0] + red[1] + red[2] + red[3] + red[4] + red[5]) * (1.0f / DD);
    const float rstd = rsqrtf(var + LEPS);

    g_xn2[row * DD + tid] = d0 * rstd * g2[tid] + b2[tid];
}

// ======================= conv core: R2 tiling + duplicated smem =======================
// Block: 192 threads, CR=16 rows. Thread = (dout-pair dp of 96, row-group rg of 2),
// 8 rows each. Input tile duplicated: ins[r][din] = {v,v} -> LDS.64 is a ready
// FFMA2 operand (no packing MOVs). All lanes of a warp read the same ins address
// (broadcast). Weight loads are coalesced LDG.64 pairs.
template<bool RELU, bool RESID>
__device__ __forceinline__ void conv_core(
    const float* __restrict__ src, const float* __restrict__ w,
    const float* __restrict__ bias, const float* __restrict__ resid,
    float* __restrict__ dst, int b, int l0, int tid)
{
    __shared__ float2 ins[(CR + 2) * DD];   // 27648 B

    #pragma unroll
    for (int r = 0; r < CR + 2; r++) {
        const int li = l0 - 1 + r;
        const float v = (li >= 0 && li < LL) ? src[(b * LL + li) * DD + tid] : 0.f;
        ins[r * DD + tid] = make_float2(v, v);
    }
    __syncthreads();

    const int dp = tid % 96;           // dout pair
    const int rg = tid / 96;           // row group (whole warps)
    const int d0 = dp * 2;
    const int rb = rg * 8;

    u64 acc[8];
    #pragma unroll
    for (int r = 0; r < 8; r++) acc[r] = 0ull;

    #pragma unroll 2
    for (int din = 0; din < DD; din++) {
        u64 xb[10];
        #pragma unroll
        for (int i = 0; i < 10; i++)
            xb[i] = *(const u64*)&ins[(rb + i) * DD + din];
        #pragma unroll
        for (int t = 0; t < 3; t++) {
            const u64 w2 = *(const u64*)(w + (t * DD + din) * DD + d0);  // LDG.64
            #pragma unroll
            for (int r = 0; r < 8; r++) acc[r] = ffma2(xb[r + t], w2, acc[r]);
        }
    }

    const float2 bv2 = *(const float2*)&bias[d0];
    #pragma unroll
    for (int r = 0; r < 8; r++) {
        const int l = l0 + rb + r;
        const bool in = (l >= 1 && l < LL - 1);
        const float2 a = unpack2(acc[r]);
        float2 o;
        if (RELU) {
            o.x = in ? fmaxf(a.x + bv2.x, 0.f) : 0.f;
            o.y = in ? fmaxf(a.y + bv2.y, 0.f) : 0.f;
        } else {
            const float2 base = *(const float2*)&resid[(b * LL + l) * DD + d0];
            o.x = in ? (base.x + a.x + bv2.x) : base.x;
            o.y = in ? (base.y + a.y + bv2.y) : base.y;
        }
        *(float2*)&dst[(b * LL + l) * DD + d0] = o;
    }
}

__global__ void __launch_bounds__(192) k_conv1(
    const float* __restrict__ w, const float* __restrict__ bias)
{
    conv_core<true, false>(g_xn2, w, bias, nullptr, g_hp,
                           blockIdx.x, blockIdx.y * CR, threadIdx.x);
}

__global__ void __launch_bounds__(192) k_conv2(
    const float* __restrict__ w, const float* __restrict__ bias,
    float* __restrict__ out)
{
    conv_core<false, true>(g_hp, w, bias, g_y1, out,
                           blockIdx.x, blockIdx.y * CR, threadIdx.x);
}

// ======================= launch =======================
extern "C" void kernel_launch(void* const* d_in, const int* in_sizes, int n_in,
                              void* d_out, int out_size)
{
    const float* x     = (const float*)d_in[0];
    const float* ln1_g = (const float*)d_in[1];
    const float* ln1_b = (const float*)d_in[2];
    const float* wq    = (const float*)d_in[3];
    const float* bq    = (const float*)d_in[4];
    const float* wk    = (const float*)d_in[5];
    const float* bk    = (const float*)d_in[6];
    const float* wv    = (const float*)d_in[7];
    const float* bv    = (const float*)d_in[8];
    const float* wo    = (const float*)d_in[9];
    const float* bo    = (const float*)d_in[10];
    const float* ln2_g = (const float*)d_in[11];
    const float* ln2_b = (const float*)d_in[12];
    const float* c1_w  = (const float*)d_in[13];
    const float* c1_b  = (const float*)d_in[14];
    const float* c2_w  = (const float*)d_in[15];
    const float* c2_b  = (const float*)d_in[16];
    float* out = (float*)d_out;

    k_ln1_qkv<<<BB * LL / RB, 288>>>(x, ln1_g, ln1_b, wq, bq, wk, bk, wv, bv);
    dim3 ag(BB * HH, LL / 256);
    k_attn<<<ag, 128>>>();
    k_proj_ln2<<<BB * LL, DD>>>(x, wo, bo, ln2_g, ln2_b);
    dim3 cg(BB, LL / CR);
    k_conv1<<<cg, 192>>>(c1_w, c1_b);
    k_conv2<<<cg, 192>>>(c2_w, c2_b, out);
}

// round 12
// speedup vs baseline: 1.2637x; 1.2637x over previous
#include <cuda_runtime.h>

#define BB 16
#define LL 2048
#define DD 192
#define HH 4
#define KH 12
#define HK 48
#define LEPS 1e-3f
#define CR 16
#define RB 32
#define NT 16   // query tiles of 128

typedef unsigned long long u64;

// -------- scratch (no allocations allowed; __device__ globals) --------
__device__ float g_q[BB * HH * LL * KH];
__device__ float g_k[BB * HH * LL * KH];
__device__ float g_v[BB * HH * LL * KH];
__device__ float g_ctx[BB * HH * LL * KH];
__device__ float g_y1[BB * LL * DD];
__device__ float g_xn2[BB * LL * DD];
__device__ float g_hp[BB * LL * DD];

// -------- packed fp32x2 helpers --------
__device__ __forceinline__ u64 ffma2(u64 a, u64 b, u64 c) {
    u64 d; asm("fma.rn.f32x2 %0, %1, %2, %3;" : "=l"(d) : "l"(a), "l"(b), "l"(c));
    return d;
}
__device__ __forceinline__ u64 fmul2(u64 a, u64 b) {
    u64 d; asm("mul.rn.f32x2 %0, %1, %2;" : "=l"(d) : "l"(a), "l"(b));
    return d;
}
__device__ __forceinline__ u64 pack2(float lo, float hi) {
    u64 r; asm("mov.b64 %0, {%1, %2};" : "=l"(r) : "f"(lo), "f"(hi));
    return r;
}
__device__ __forceinline__ float2 unpack2(u64 v) {
    float2 f; asm("mov.b64 {%0, %1}, %2;" : "=f"(f.x), "=f"(f.y) : "l"(v));
    return f;
}
__device__ __forceinline__ float fast_ex2(float x) {
    float y; asm("ex2.approx.f32 %0, %1;" : "=f"(y) : "f"(x)); return y;
}

// ======================= K1: LN1 + QKV projection (R2) =======================
__global__ void __launch_bounds__(288) k_ln1_qkv(
    const float* __restrict__ x,
    const float* __restrict__ ln_g, const float* __restrict__ ln_b,
    const float* __restrict__ wq, const float* __restrict__ bq,
    const float* __restrict__ wk, const float* __restrict__ bk,
    const float* __restrict__ wv, const float* __restrict__ bv)
{
    __shared__ float xsT[DD][RB + 2];
    __shared__ float mean_s[RB], rstd_s[RB];
    const int row0 = blockIdx.x * RB;
    const int tid  = threadIdx.x;

    for (int idx = tid; idx < RB * DD; idx += 288) {
        const int r = idx / DD, c = idx - r * DD;
        xsT[c][r] = x[(row0 + r) * DD + c];
    }
    __syncthreads();

    if (tid < RB) {
        float s = 0.f, s2 = 0.f;
        #pragma unroll 8
        for (int c = 0; c < DD; c++) {
            const float v = xsT[c][tid];
            s += v; s2 = fmaf(v, v, s2);
        }
        const float m = s * (1.0f / DD);
        const float var = s2 * (1.0f / DD) - m * m;
        mean_s[tid] = m;
        rstd_s[tid] = rsqrtf(var + LEPS);
    }
    __syncthreads();

    for (int idx = tid; idx < RB * DD; idx += 288) {
        const int r = idx & (RB - 1), c = idx >> 5;
        xsT[c][r] = (xsT[c][r] - mean_s[r]) * rstd_s[r] * ln_g[c] + ln_b[c];
    }
    __syncthreads();

    const int jj = tid % 144;
    const int rg = tid / 144;
    const int m  = jj / HK;
    const int j  = jj - m * HK;
    const float* w  = (m == 0) ? wq : (m == 1) ? wk : wv;
    const float* bb = (m == 0) ? bq : (m == 1) ? bk : bv;
    const float bias = bb[j];
    const int rbase = rg * 16;

    u64 acc[8];
    const u64 binit = pack2(bias, bias);
    #pragma unroll
    for (int p = 0; p < 8; p++) acc[p] = binit;

    #pragma unroll 4
    for (int d = 0; d < DD; d++) {
        const float wv_ = w[d * HK + j];
        const u64 w2 = pack2(wv_, wv_);
        const u64* xp = (const u64*)&xsT[d][rbase];
        #pragma unroll
        for (int p = 0; p < 8; p++) acc[p] = ffma2(xp[p], w2, acc[p]);
    }

    float* dst = (m == 0) ? g_q : (m == 1) ? g_k : g_v;
    const int bi = row0 / LL;
    const int l0 = row0 - bi * LL;
    const int h = j / KH, kk = j - h * KH;
    float* o = dst + (((bi * HH + h) * LL) + l0 + rbase) * KH + kk;
    #pragma unroll
    for (int p = 0; p < 8; p++) {
        const float2 f = unpack2(acc[p]);
        o[(2 * p) * KH]     = f.x;
        o[(2 * p + 1) * KH] = f.y;
    }
}

// ======================= K2: causal attention, balanced tile pairs =======================
// Block y handles query tiles qtA = y and qtB = NT-1-y (one query of each per
// thread). Every block does exactly qtB+1 = 16-y K/V tiles and (y+1)+(16-y) = 17
// tile-passes of softmax work -> perfectly balanced grid (512 blocks).
__device__ __forceinline__ void att_step(const u64* __restrict__ kp,
                                         const u64* __restrict__ vp,
                                         const u64* __restrict__ q2,
                                         u64* __restrict__ acc, float& ssum)
{
    u64 s2 = fmul2(q2[0], kp[0]);
    s2 = ffma2(q2[1], kp[1], s2);
    s2 = ffma2(q2[2], kp[2], s2);
    s2 = ffma2(q2[3], kp[3], s2);
    s2 = ffma2(q2[4], kp[4], s2);
    s2 = ffma2(q2[5], kp[5], s2);
    const float2 sf = unpack2(s2);
    const float p = fast_ex2(sf.x + sf.y);
    ssum += p;
    const u64 p2 = pack2(p, p);
    acc[0] = ffma2(p2, vp[0], acc[0]);
    acc[1] = ffma2(p2, vp[1], acc[1]);
    acc[2] = ffma2(p2, vp[2], acc[2]);
    acc[3] = ffma2(p2, vp[3], acc[3]);
    acc[4] = ffma2(p2, vp[4], acc[4]);
    acc[5] = ffma2(p2, vp[5], acc[5]);
}

__global__ void __launch_bounds__(128) k_attn()
{
    __shared__ float ks[128 * 12];
    __shared__ float vs[128 * 12];
    const int bh  = blockIdx.x;
    const int qtA = blockIdx.y;            // 0..7
    const int qtB = NT - 1 - qtA;          // 15..8  (qtA < qtB always)
    const int tid = threadIdx.x;
    const int lA  = qtA * 128 + tid;
    const int lB  = qtB * 128 + tid;

    const float qsc = 0.41647020f;    // log2(e) / sqrt(12)
    const u64 qsc2 = pack2(qsc, qsc);
    u64 qA[6], qB[6];
    {
        const u64* pa = (const u64*)(g_q + (bh * LL + lA) * KH);
        const u64* pb = (const u64*)(g_q + (bh * LL + lB) * KH);
        #pragma unroll
        for (int i = 0; i < 6; i++) { qA[i] = fmul2(pa[i], qsc2); qB[i] = fmul2(pb[i], qsc2); }
    }

    u64 accA[6], accB[6];
    #pragma unroll
    for (int i = 0; i < 6; i++) { accA[i] = 0ull; accB[i] = 0ull; }
    float ssA = 0.f, ssB = 0.f;

    for (int kt = 0; kt <= qtB; kt++) {
        const float4* kp4 = (const float4*)(g_k + (bh * LL + kt * 128) * KH);
        const float4* vp4 = (const float4*)(g_v + (bh * LL + kt * 128) * KH);
        __syncthreads();
        ((float4*)ks)[tid * 3 + 0] = kp4[tid * 3 + 0];
        ((float4*)ks)[tid * 3 + 1] = kp4[tid * 3 + 1];
        ((float4*)ks)[tid * 3 + 2] = kp4[tid * 3 + 2];
        ((float4*)vs)[tid * 3 + 0] = vp4[tid * 3 + 0];
        ((float4*)vs)[tid * 3 + 1] = vp4[tid * 3 + 1];
        ((float4*)vs)[tid * 3 + 2] = vp4[tid * 3 + 2];
        __syncthreads();

        if (kt < qtA) {
            // full tile for both queries
            #pragma unroll 2
            for (int m = 0; m < 128; m++) {
                const u64* kp = (const u64*)(ks + m * 12);
                const u64* vp = (const u64*)(vs + m * 12);
                att_step(kp, vp, qA, accA, ssA);
                att_step(kp, vp, qB, accB, ssB);
            }
        } else if (kt == qtA) {
            // diagonal for A, full for B
            for (int m = 0; m <= tid; m++) {
                const u64* kp = (const u64*)(ks + m * 12);
                const u64* vp = (const u64*)(vs + m * 12);
                att_step(kp, vp, qA, accA, ssA);
                att_step(kp, vp, qB, accB, ssB);
            }
            for (int m = tid + 1; m < 128; m++) {
                const u64* kp = (const u64*)(ks + m * 12);
                const u64* vp = (const u64*)(vs + m * 12);
                att_step(kp, vp, qB, accB, ssB);
            }
        } else if (kt < qtB) {
            // full tile for B only
            #pragma unroll 2
            for (int m = 0; m < 128; m++) {
                const u64* kp = (const u64*)(ks + m * 12);
                const u64* vp = (const u64*)(vs + m * 12);
                att_step(kp, vp, qB, accB, ssB);
            }
        } else {
            // diagonal for B
            for (int m = 0; m <= tid; m++) {
                const u64* kp = (const u64*)(ks + m * 12);
                const u64* vp = (const u64*)(vs + m * 12);
                att_step(kp, vp, qB, accB, ssB);
            }
        }
    }

    const float invA = 1.0f / ssA;
    const float invB = 1.0f / ssB;
    const u64 iA = pack2(invA, invA);
    const u64 iB = pack2(invB, invB);
    u64* ca = (u64*)(g_ctx + (bh * LL + lA) * KH);
    u64* cb = (u64*)(g_ctx + (bh * LL + lB) * KH);
    #pragma unroll
    for (int i = 0; i < 6; i++) { ca[i] = fmul2(accA[i], iA); cb[i] = fmul2(accB[i], iB); }
}

// ======================= K3: out-proj + residual + LN2 (R2) =======================
__global__ void __launch_bounds__(DD) k_proj_ln2(
    const float* __restrict__ x,
    const float* __restrict__ wo, const float* __restrict__ bo,
    const float* __restrict__ g2, const float* __restrict__ b2)
{
    __shared__ float cs[HK];
    __shared__ float red[8];
    const int row = blockIdx.x;
    const int tid = threadIdx.x;
    const int bi = row / LL, l = row % LL;

    if (tid < HK) {
        const int h = tid / KH, kk = tid % KH;
        cs[tid] = g_ctx[((bi * HH + h) * LL + l) * KH + kk];
    }
    __syncthreads();

    float y = x[row * DD + tid] + bo[tid];
    #pragma unroll 8
    for (int j = 0; j < HK; j++) y = fmaf(cs[j], wo[j * DD + tid], y);
    g_y1[row * DD + tid] = y;

    float s = y;
    #pragma unroll
    for (int o = 16; o > 0; o >>= 1) s += __shfl_xor_sync(0xffffffffu, s, o);
    if ((tid & 31) == 0) red[tid >> 5] = s;
    __syncthreads();
    const float mean = (red[0] + red[1] + red[2] + red[3] + red[4] + red[5]) * (1.0f / DD);
    const float d0 = y - mean;
    __syncthreads();
    float s2 = d0 * d0;
    #pragma unroll
    for (int o = 16; o > 0; o >>= 1) s2 += __shfl_xor_sync(0xffffffffu, s2, o);
    if ((tid & 31) == 0) red[tid >> 5] = s2;
    __syncthreads();
    const float var = (red[0] + red[1] + red[2] + red[3] + red[4] + red[5]) * (1.0f / DD);
    const float rstd = rsqrtf(var + LEPS);

    g_xn2[row * DD + tid] = d0 * rstd * g2[tid] + b2[tid];
}

// ======================= conv core (R2: pack-MOV FFMA2, 167.6us proven) =======================
template<bool RELU, bool RESID>
__device__ __forceinline__ void conv_core(
    const float* __restrict__ src, const float* __restrict__ w,
    const float* __restrict__ bias, const float* __restrict__ resid,
    float* __restrict__ dst, int b, int l0, int tid)
{
    __shared__ float ins[CR + 2][DD];

    #pragma unroll
    for (int r = 0; r < CR + 2; r++) {
        const int li = l0 - 1 + r;
        ins[r][tid] = (li >= 0 && li < LL) ? src[(b * LL + li) * DD + tid] : 0.f;
    }
    __syncthreads();

    const int dp = tid % 96;           // dout pair
    const int rg = tid / 96;           // row group 0/1 (whole warps)
    const int d0 = dp * 2;
    const int rb = rg * 8;

    u64 acc[8];
    #pragma unroll
    for (int r = 0; r < 8; r++) acc[r] = 0ull;

    for (int din = 0; din < DD; din++) {
        u64 xb[10];
        #pragma unroll
        for (int i = 0; i < 10; i++) {
            const float xv_ = ins[rb + i][din];     // warp-uniform: broadcast
            xb[i] = pack2(xv_, xv_);
        }
        #pragma unroll
        for (int t = 0; t < 3; t++) {
            const u64 w2 = *(const u64*)(w + (t * DD + din) * DD + d0);  // LDG.64
            #pragma unroll
            for (int r = 0; r < 8; r++) acc[r] = ffma2(xb[r + t], w2, acc[r]);
        }
    }

    const float2 bv2 = *(const float2*)&bias[d0];
    #pragma unroll
    for (int r = 0; r < 8; r++) {
        const int l = l0 + rb + r;
        const float2 a = unpack2(acc[r]);
        const bool in = (l >= 1 && l < LL - 1);
        float2 o;
        if (RELU) {
            o.x = in ? fmaxf(a.x + bv2.x, 0.f) : 0.f;
            o.y = in ? fmaxf(a.y + bv2.y, 0.f) : 0.f;
        } else {
            const float2 base = *(const float2*)&resid[(b * LL + l) * DD + d0];
            o.x = in ? (base.x + a.x + bv2.x) : base.x;
            o.y = in ? (base.y + a.y + bv2.y) : base.y;
        }
        *(float2*)&dst[(b * LL + l) * DD + d0] = o;
    }
}

__global__ void __launch_bounds__(192) k_conv1(
    const float* __restrict__ w, const float* __restrict__ bias)
{
    conv_core<true, false>(g_xn2, w, bias, nullptr, g_hp,
                           blockIdx.x, blockIdx.y * CR, threadIdx.x);
}

__global__ void __launch_bounds__(192) k_conv2(
    const float* __restrict__ w, const float* __restrict__ bias,
    float* __restrict__ out)
{
    conv_core<false, true>(g_hp, w, bias, g_y1, out,
                           blockIdx.x, blockIdx.y * CR, threadIdx.x);
}

// ======================= launch =======================
extern "C" void kernel_launch(void* const* d_in, const int* in_sizes, int n_in,
                              void* d_out, int out_size)
{
    const float* x     = (const float*)d_in[0];
    const float* ln1_g = (const float*)d_in[1];
    const float* ln1_b = (const float*)d_in[2];
    const float* wq    = (const float*)d_in[3];
    const float* bq    = (const float*)d_in[4];
    const float* wk    = (const float*)d_in[5];
    const float* bk    = (const float*)d_in[6];
    const float* wv    = (const float*)d_in[7];
    const float* bv    = (const float*)d_in[8];
    const float* wo    = (const float*)d_in[9];
    const float* bo    = (const float*)d_in[10];
    const float* ln2_g = (const float*)d_in[11];
    const float* ln2_b = (const float*)d_in[12];
    const float* c1_w  = (const float*)d_in[13];
    const float* c1_b  = (const float*)d_in[14];
    const float* c2_w  = (const float*)d_in[15];
    const float* c2_b  = (const float*)d_in[16];
    float* out = (float*)d_out;

    k_ln1_qkv<<<BB * LL / RB, 288>>>(x, ln1_g, ln1_b, wq, bq, wk, bk, wv, bv);
    dim3 ag(BB * HH, NT / 2);
    k_attn<<<ag, 128>>>();
    k_proj_ln2<<<BB * LL, DD>>>(x, wo, bo, ln2_g, ln2_b);
    dim3 cg(BB, LL / CR);
    k_conv1<<<cg, 192>>>(c1_w, c1_b);
    k_conv2<<<cg, 192>>>(c2_w, c2_b, out);
}